// round 7
// baseline (speedup 1.0000x reference)
#include <cuda_runtime.h>
#include <math.h>

// Per-point min squared distances as float bits (nonnegative => order-preserving
// as unsigned). [0..N) = pred->gt, [N..2N) = gt->pred.
#define MAX_PTS 65536
__device__ unsigned g_minbits[2 * MAX_PTS];

#define THREADS 512
#define TXP 8                  // packed x-pairs per thread
#define TX (2 * TXP)           // 16 x-points per thread
#define XTILE (THREADS * TX)   // 8192 x-points per block
#define YT 512                 // y points resident in smem per tile

// ---- f32x2 helpers (Blackwell packed fp32) ----
__device__ __forceinline__ unsigned long long ffma2(
    unsigned long long a, unsigned long long b, unsigned long long c) {
    unsigned long long d;
    asm("fma.rn.f32x2 %0, %1, %2, %3;" : "=l"(d) : "l"(a), "l"(b), "l"(c));
    return d;
}
__device__ __forceinline__ unsigned long long packdup(float f) {
    unsigned long long u = __float_as_uint(f);
    return u | (u << 32);
}
__device__ __forceinline__ unsigned long long packab(float a, float b) {
    return ((unsigned long long)__float_as_uint(b) << 32) |
           (unsigned long long)__float_as_uint(a);
}
__device__ __forceinline__ float lo32f(unsigned long long v) {
    return __uint_as_float((unsigned)v);
}
__device__ __forceinline__ float hi32f(unsigned long long v) {
    return __uint_as_float((unsigned)(v >> 32));
}

__global__ void init_kernel(float* out, int total) {
    int i = blockIdx.x * blockDim.x + threadIdx.x;
    if (i < total) g_minbits[i] = 0x7F800000u;  // +inf
    if (i == 0) out[0] = 0.0f;
}

// Fused bidirectional pass. blockIdx.z selects direction.
// d2 = sx + (sy - 2 x.y); inner loop tracks acc = sy - 2 x.y packed 2 x-points
// per f32x2 lane-pair: 3 FFMA2 + 2 FMNMX per 2 pairs.
__global__ __launch_bounds__(THREADS, 1) void chamfer_pass_kernel(
    const float* __restrict__ pred, const float* __restrict__ gt,
    int N, int ychunk)
{
    // per y: [0] = (bx,by) = ((-2y0,-2y0),(-2y1,-2y1)); [1] = (bz,bw)
    __shared__ ulonglong2 sy[YT][2];

    const float* X = (blockIdx.z == 0) ? pred : gt;
    const float* Y = (blockIdx.z == 0) ? gt : pred;
    const int outOff = (blockIdx.z == 0) ? 0 : N;

    const int xbase = blockIdx.x * XTILE;
    const int ybeg = blockIdx.y * ychunk;
    const int yend = min(ybeg + ychunk, N);

    unsigned long long xp0[TXP], xp1[TXP], xp2[TXP];
    float mn[TX];
#pragma unroll
    for (int k = 0; k < TXP; k++) {
        float a0 = 0.f, a1 = 0.f, a2 = 0.f, b0 = 0.f, b1 = 0.f, b2 = 0.f;
        int xa = xbase + (2 * k + 0) * THREADS + threadIdx.x;
        int xb = xbase + (2 * k + 1) * THREADS + threadIdx.x;
        if (xa < N) { a0 = X[3 * xa]; a1 = X[3 * xa + 1]; a2 = X[3 * xa + 2]; }
        if (xb < N) { b0 = X[3 * xb]; b1 = X[3 * xb + 1]; b2 = X[3 * xb + 2]; }
        xp0[k] = packab(a0, b0);
        xp1[k] = packab(a1, b1);
        xp2[k] = packab(a2, b2);
        mn[2 * k] = INFINITY;
        mn[2 * k + 1] = INFINITY;
    }

    for (int ybase = ybeg; ybase < yend; ybase += YT) {
        const int cnt = min(YT, yend - ybase);
        __syncthreads();
        for (int j = threadIdx.x; j < cnt; j += THREADS) {
            int yi = ybase + j;
            float a = Y[3 * yi], b = Y[3 * yi + 1], c = Y[3 * yi + 2];
            float w = fmaf(a, a, fmaf(b, b, c * c));
            sy[j][0] = make_ulonglong2(packdup(-2.0f * a), packdup(-2.0f * b));
            sy[j][1] = make_ulonglong2(packdup(-2.0f * c), packdup(w));
        }
        __syncthreads();

#pragma unroll 2
        for (int j = 0; j < cnt; j++) {
            ulonglong2 v01 = sy[j][0];  // bx, by
            ulonglong2 v23 = sy[j][1];  // bz, bw
#pragma unroll
            for (int k = 0; k < TXP; k++) {
                unsigned long long acc = ffma2(xp0[k], v01.x, v23.y);
                acc = ffma2(xp1[k], v01.y, acc);
                acc = ffma2(xp2[k], v23.x, acc);
                mn[2 * k]     = fminf(mn[2 * k],     lo32f(acc));
                mn[2 * k + 1] = fminf(mn[2 * k + 1], hi32f(acc));
            }
        }
    }

#pragma unroll
    for (int k = 0; k < TXP; k++) {
        int xa = xbase + (2 * k + 0) * THREADS + threadIdx.x;
        int xb = xbase + (2 * k + 1) * THREADS + threadIdx.x;
        if (xa < N) {
            float a0 = lo32f(xp0[k]), a1 = lo32f(xp1[k]), a2 = lo32f(xp2[k]);
            float sx = fmaf(a0, a0, fmaf(a1, a1, a2 * a2));
            float d2 = fmaxf(mn[2 * k] + sx, 0.0f);
            atomicMin(&g_minbits[outOff + xa], __float_as_uint(d2));
        }
        if (xb < N) {
            float b0 = hi32f(xp0[k]), b1 = hi32f(xp1[k]), b2 = hi32f(xp2[k]);
            float sx = fmaf(b0, b0, fmaf(b1, b1, b2 * b2));
            float d2 = fmaxf(mn[2 * k + 1] + sx, 0.0f);
            atomicMin(&g_minbits[outOff + xb], __float_as_uint(d2));
        }
    }
}

// Multi-block reduction: sum sqrt(min d2)/N into out via atomicAdd.
__global__ void chamfer_reduce_kernel(float* __restrict__ out, int N) {
    __shared__ float warpsum[32];
    float s = 0.0f;
    for (int i = blockIdx.x * blockDim.x + threadIdx.x; i < 2 * N;
         i += gridDim.x * blockDim.x) {
        float d2 = fmaxf(__uint_as_float(g_minbits[i]), 0.0f);
        s += sqrtf(d2);
    }
    for (int off = 16; off > 0; off >>= 1)
        s += __shfl_down_sync(0xFFFFFFFFu, s, off);
    int wid = threadIdx.x >> 5;
    int lid = threadIdx.x & 31;
    if (lid == 0) warpsum[wid] = s;
    __syncthreads();
    int nwarps = blockDim.x >> 5;
    if (wid == 0) {
        float v = (lid < nwarps) ? warpsum[lid] : 0.0f;
        for (int off = 16; off > 0; off >>= 1)
            v += __shfl_down_sync(0xFFFFFFFFu, v, off);
        if (lid == 0) atomicAdd(out, v / (float)N);  // (sum0+sum1)/N
    }
}

extern "C" void kernel_launch(void* const* d_in, const int* in_sizes, int n_in,
                              void* d_out, int out_size) {
    const float* pred = (const float*)d_in[0];
    const float* gt   = (const float*)d_in[1];
    float* out = (float*)d_out;

    const int N = in_sizes[0] / 3;  // 16384

    // 1) init min buffers (+inf) and zero out
    {
        int total = 2 * N;
        init_kernel<<<(total + 511) / 512, 512>>>(out, total);
    }

    // 2) fused bidirectional pass: target ~144 blocks = 1 wave on 148 SMs
    {
        int gx = (N + XTILE - 1) / XTILE;               // 2 for N=16384
        int gy = 72 / gx; if (gy < 1) gy = 1;           // 36
        int ychunk = (N + gy - 1) / gy;                 // 456 (<= YT)
        dim3 grid(gx, gy, 2);
        chamfer_pass_kernel<<<grid, THREADS>>>(pred, gt, N, ychunk);
    }

    // 3) scalar reduction, multi-block
    chamfer_reduce_kernel<<<48, 256>>>(out, N);
}